// round 8
// baseline (speedup 1.0000x reference)
#include <cuda_runtime.h>
#include <cuda_bf16.h>
#include <math.h>
#include <cstdint>

#define T_STEPS 256
#define BSZ 32
#define VOCAB 32000
#define EMB 512
#define HID 1024
#define G4 4096
#define TB (T_STEPS*BSZ)   // 8192
#define NBLK 128

// ---------------- scratch (device globals; no allocation allowed) ----------------
__device__ float g_gates[(size_t)TB*G4];             // 134 MB input-projection gates
__device__ __nv_bfloat16 g_ahi[(size_t)TB*HID];      // A split hi (activations, reused per layer)
__device__ __nv_bfloat16 g_alo[(size_t)TB*HID];      // A split lo
__device__ __nv_bfloat16 g_wthi[(size_t)G4*HID];     // layer Wx^T hi
__device__ __nv_bfloat16 g_wtlo[(size_t)G4*HID];     // layer Wx^T lo
__device__ __nv_bfloat16 g_whthi[(size_t)G4*HID];    // layer Wh^T hi
__device__ __nv_bfloat16 g_whtlo[(size_t)G4*HID];    // layer Wh^T lo
__device__ __nv_bfloat16 g_wdthi[(size_t)VOCAB*HID]; // decoder W^T hi
__device__ __nv_bfloat16 g_wdtlo[(size_t)VOCAB*HID]; // decoder W^T lo
__device__ __nv_bfloat16 g_hb[2*2*BSZ*HID];          // h bf16 [par][hi/lo][32*1024]

// monotonic grid-barrier counter
__device__ unsigned long long g_ctr1;

// ---------------- helpers ----------------
__device__ __forceinline__ uint32_t smem_u32(const void* p){
    uint32_t a; asm("{ .reg .u64 t; cvta.to.shared.u64 t, %1; cvt.u32.u64 %0, t; }" : "=r"(a) : "l"(p));
    return a;
}
#define CP_ASYNC16(dst, src) asm volatile("cp.async.cg.shared.global [%0], [%1], 16;" :: "r"(dst), "l"(src))
#define CP_COMMIT()  asm volatile("cp.async.commit_group;" ::: "memory")

__device__ __forceinline__ void ldsm4(uint32_t* r, uint32_t addr){
    asm volatile("ldmatrix.sync.aligned.m8n8.x4.shared.b16 {%0,%1,%2,%3}, [%4];"
        : "=r"(r[0]), "=r"(r[1]), "=r"(r[2]), "=r"(r[3]) : "r"(addr));
}
__device__ __forceinline__ void mma16816(float* c, const uint32_t* a, const uint32_t* b){
    asm volatile("mma.sync.aligned.m16n8k16.row.col.f32.bf16.bf16.f32 "
        "{%0,%1,%2,%3}, {%4,%5,%6,%7}, {%8,%9}, {%0,%1,%2,%3};"
        : "+f"(c[0]), "+f"(c[1]), "+f"(c[2]), "+f"(c[3])
        : "r"(a[0]), "r"(a[1]), "r"(a[2]), "r"(a[3]), "r"(b[0]), "r"(b[1]));
}
__device__ __forceinline__ float sigm(float x){ return 1.0f / (1.0f + expf(-x)); }

// ---------------- embedding gather + bf16 hi/lo split ----------------
__global__ void embed_split(const int* __restrict__ data, const float* __restrict__ emb,
                            __nv_bfloat16* __restrict__ hi, __nv_bfloat16* __restrict__ lo){
    int idx = blockIdx.x * 256 + threadIdx.x;     // over TB*EMB/4 float4s
    int e4 = idx & (EMB/4 - 1);
    int tb = idx >> 7;                            // EMB/4 = 128
    float4 v = ((const float4*)(emb + (size_t)data[tb]*EMB))[e4];
    __nv_bfloat16 h0 = __float2bfloat16(v.x), h1 = __float2bfloat16(v.y);
    __nv_bfloat16 h2 = __float2bfloat16(v.z), h3 = __float2bfloat16(v.w);
    __nv_bfloat16 l0 = __float2bfloat16(v.x - __bfloat162float(h0));
    __nv_bfloat16 l1 = __float2bfloat16(v.y - __bfloat162float(h1));
    __nv_bfloat16 l2 = __float2bfloat16(v.z - __bfloat162float(h2));
    __nv_bfloat16 l3 = __float2bfloat16(v.w - __bfloat162float(h3));
    ((__nv_bfloat162*)hi)[2*idx]   = __nv_bfloat162(h0, h1);
    ((__nv_bfloat162*)hi)[2*idx+1] = __nv_bfloat162(h2, h3);
    ((__nv_bfloat162*)lo)[2*idx]   = __nv_bfloat162(l0, l1);
    ((__nv_bfloat162*)lo)[2*idx+1] = __nv_bfloat162(l2, l3);
}

// ---------------- weight transpose + split: W[K,N] -> Wt_hi/lo[N,K] ----------------
__global__ void wtr_k(const float* __restrict__ W, __nv_bfloat16* __restrict__ thi,
                      __nv_bfloat16* __restrict__ tlo, int K, int N){
    __shared__ float s[32][33];
    int tx = threadIdx.x, ty = threadIdx.y;
    int n0 = blockIdx.x * 32, k0 = blockIdx.y * 32;
    #pragma unroll
    for (int j = 0; j < 32; j += 8)
        s[ty+j][tx] = W[(size_t)(k0+ty+j)*N + n0 + tx];
    __syncthreads();
    #pragma unroll
    for (int j = 0; j < 32; j += 8){
        float v = s[tx][ty+j];
        __nv_bfloat16 h = __float2bfloat16(v);
        __nv_bfloat16 l = __float2bfloat16(v - __bfloat162float(h));
        size_t o = (size_t)(n0+ty+j)*K + k0 + tx;
        thi[o] = h;
        tlo[o] = l;
    }
}

// ---------------- bf16 3-split GEMM on mma.sync ----------------
// Grid: x = M/128 (fast), y = N/128 -> consecutive blocks share the B panel.
#define BKC 32
#define STRIDE 40
#define MAT_B (128*STRIDE*2)
#define BUF_BYTES (4*MAT_B)
#define MMA_SMEM (2*BUF_BYTES + 512)

__global__ __launch_bounds__(256, 2)
void gemm_mma(const __nv_bfloat16* __restrict__ Ahi, const __nv_bfloat16* __restrict__ Alo,
              const __nv_bfloat16* __restrict__ Bhi, const __nv_bfloat16* __restrict__ Blo,
              const float* __restrict__ bias, float* __restrict__ C,
              int M, int N, int K)
{
    extern __shared__ char smem[];
    const uint32_t sb = smem_u32(smem);
    const int tid  = threadIdx.x;
    const int wid  = tid >> 5;
    const int lane = tid & 31;
    const int m0 = blockIdx.x * 128;
    const int n0 = blockIdx.y * 128;
    const int warp_m = (wid & 3) * 32;
    const int warp_n = (wid >> 2) * 64;

    float* biasS = (float*)(smem + 2*BUF_BYTES);
    if (tid < 128) biasS[tid] = bias[n0 + tid];

    const int r0v = tid >> 2,          kv0 = (tid & 3) * 8;
    const int r1v = (tid + 256) >> 2,  kv1 = kv0;
    const uint32_t d0 = (uint32_t)(r0v*STRIDE + kv0) * 2;
    const uint32_t d1 = (uint32_t)(r1v*STRIDE + kv1) * 2;

    const __nv_bfloat16* a0p = Ahi + (size_t)(m0 + r0v)*K + kv0;
    const __nv_bfloat16* a1p = Ahi + (size_t)(m0 + r1v)*K + kv1;
    const __nv_bfloat16* l0p = Alo + (size_t)(m0 + r0v)*K + kv0;
    const __nv_bfloat16* l1p = Alo + (size_t)(m0 + r1v)*K + kv1;
    const __nv_bfloat16* b0p = Bhi + (size_t)(n0 + r0v)*K + kv0;
    const __nv_bfloat16* b1p = Bhi + (size_t)(n0 + r1v)*K + kv1;
    const __nv_bfloat16* c0p = Blo + (size_t)(n0 + r0v)*K + kv0;
    const __nv_bfloat16* c1p = Blo + (size_t)(n0 + r1v)*K + kv1;

    const int lq = lane >> 3, lr = lane & 7;
    uint32_t offA[2], offB[4];
    #pragma unroll
    for (int mt = 0; mt < 2; mt++)
        offA[mt] = (uint32_t)((warp_m + mt*16 + (lq&1)*8 + lr)*STRIDE + (lq>>1)*8) * 2;
    #pragma unroll
    for (int np = 0; np < 4; np++)
        offB[np] = (uint32_t)((warp_n + np*16 + (lq>>1)*8 + lr)*STRIDE + (lq&1)*8) * 2;

    float acc[2][8][4];
    #pragma unroll
    for (int mt = 0; mt < 2; mt++)
        #pragma unroll
        for (int nt = 0; nt < 8; nt++)
            #pragma unroll
            for (int j = 0; j < 4; j++) acc[mt][nt][j] = 0.f;

    const int NC = K / BKC;

    {
        uint32_t bb = sb;
        CP_ASYNC16(bb + 0*MAT_B + d0, a0p); CP_ASYNC16(bb + 0*MAT_B + d1, a1p);
        CP_ASYNC16(bb + 1*MAT_B + d0, l0p); CP_ASYNC16(bb + 1*MAT_B + d1, l1p);
        CP_ASYNC16(bb + 2*MAT_B + d0, b0p); CP_ASYNC16(bb + 2*MAT_B + d1, b1p);
        CP_ASYNC16(bb + 3*MAT_B + d0, c0p); CP_ASYNC16(bb + 3*MAT_B + d1, c1p);
        CP_COMMIT();
    }

    for (int c = 0; c < NC; c++){
        if (c + 1 < NC){
            uint32_t bb = sb + ((c+1) & 1) * BUF_BYTES;
            int ko = (c+1) * BKC;
            CP_ASYNC16(bb + 0*MAT_B + d0, a0p + ko); CP_ASYNC16(bb + 0*MAT_B + d1, a1p + ko);
            CP_ASYNC16(bb + 1*MAT_B + d0, l0p + ko); CP_ASYNC16(bb + 1*MAT_B + d1, l1p + ko);
            CP_ASYNC16(bb + 2*MAT_B + d0, b0p + ko); CP_ASYNC16(bb + 2*MAT_B + d1, b1p + ko);
            CP_ASYNC16(bb + 3*MAT_B + d0, c0p + ko); CP_ASYNC16(bb + 3*MAT_B + d1, c1p + ko);
            CP_COMMIT();
            asm volatile("cp.async.wait_group 1;" ::: "memory");
        } else {
            asm volatile("cp.async.wait_group 0;" ::: "memory");
        }
        __syncthreads();

        const uint32_t ab = sb + (c & 1) * BUF_BYTES;
        const uint32_t al = ab + MAT_B;
        const uint32_t bh = ab + 2*MAT_B;
        const uint32_t bl = ab + 3*MAT_B;

        #pragma unroll
        for (int ks = 0; ks < 2; ks++){
            const uint32_t ko = ks * 32;
            uint32_t rah[2][4], ral[2][4];
            #pragma unroll
            for (int mt = 0; mt < 2; mt++){
                ldsm4(rah[mt], ab + offA[mt] + ko);
                ldsm4(ral[mt], al + offA[mt] + ko);
            }
            uint32_t rbh[8][2], rbl[8][2];
            #pragma unroll
            for (int np = 0; np < 4; np++){
                uint32_t t[4];
                ldsm4(t, bh + offB[np] + ko);
                rbh[np*2][0] = t[0];   rbh[np*2][1] = t[1];
                rbh[np*2+1][0] = t[2]; rbh[np*2+1][1] = t[3];
                ldsm4(t, bl + offB[np] + ko);
                rbl[np*2][0] = t[0];   rbl[np*2][1] = t[1];
                rbl[np*2+1][0] = t[2]; rbl[np*2+1][1] = t[3];
            }
            #pragma unroll
            for (int mt = 0; mt < 2; mt++)
                #pragma unroll
                for (int nt = 0; nt < 8; nt++){
                    mma16816(acc[mt][nt], rah[mt], rbh[nt]);
                    mma16816(acc[mt][nt], rah[mt], rbl[nt]);
                    mma16816(acc[mt][nt], ral[mt], rbh[nt]);
                }
        }
        __syncthreads();
    }

    #pragma unroll
    for (int mt = 0; mt < 2; mt++){
        int row = m0 + warp_m + mt*16 + (lane >> 2);
        #pragma unroll
        for (int nt = 0; nt < 8; nt++){
            int lc = warp_n + nt*8 + (lane & 3)*2;
            float bA = biasS[lc], bB = biasS[lc+1];
            float2 v0 = make_float2(acc[mt][nt][0] + bA, acc[mt][nt][1] + bB);
            float2 v1 = make_float2(acc[mt][nt][2] + bA, acc[mt][nt][3] + bB);
            *(float2*)(C + (size_t)row*N + n0 + lc)       = v0;
            *(float2*)(C + (size_t)(row+8)*N + n0 + lc)   = v1;
        }
    }
}

// ---------------- persistent tensor-core LSTM layer ----------------
// 128 blocks, 256 thr / 8 warps. Block owns 32 gate cols (4 gates x 8 units).
// Wh^T bf16 fragments live in registers. h exchanged via small global double buffer.
// Layer output written directly as bf16 hi/lo rows of the next GEMM's A operand.
__global__ __launch_bounds__(256, 1)
void lstm_layer_mma(const float* __restrict__ gates_all,    // [T][32][4096]
                    const __nv_bfloat16* __restrict__ whhi,  // [4096][1024]
                    const __nv_bfloat16* __restrict__ whlo,
                    __nv_bfloat16* __restrict__ ohi,         // [T*32][1024] output split hi
                    __nv_bfloat16* __restrict__ olo,         // [T*32][1024] output split lo
                    __nv_bfloat16* __restrict__ hb)          // [2][2][32*1024]
{
    __shared__ float red[8][32][34];
    __shared__ float sc[8][33];
    __shared__ unsigned long long s_base;

    const int tid  = threadIdx.x;
    const int w    = tid >> 5;
    const int lane = tid & 31;
    const int hu0  = blockIdx.x * 8;
    const int wk0  = w * 128;
    const int qr   = lane >> 2;
    const int qc   = (lane & 3) * 2;

    // B fragments (Wh^T hi/lo), once per layer
    uint32_t bh[4][8][2], bl[4][8][2];
    #pragma unroll
    for (int g = 0; g < 4; g++){
        const size_t col = (size_t)(g*1024 + hu0 + qr);
        #pragma unroll
        for (int kt = 0; kt < 8; kt++){
            const size_t kk = (size_t)wk0 + kt*16 + qc;
            bh[g][kt][0] = *(const uint32_t*)(whhi + col*HID + kk);
            bh[g][kt][1] = *(const uint32_t*)(whhi + col*HID + kk + 8);
            bl[g][kt][0] = *(const uint32_t*)(whlo + col*HID + kk);
            bl[g][kt][1] = *(const uint32_t*)(whlo + col*HID + kk + 8);
        }
    }

    for (int i = tid; i < 8*33; i += 256) ((float*)sc)[i] = 0.f;
    if (tid == 0) s_base = *(volatile unsigned long long*)&g_ctr1;
    __syncthreads();
    const unsigned long long base = s_base;

    const int ub = tid & 31;    // update: batch
    const int uj = tid >> 5;    // update: unit 0..7
    const float* ginp = gates_all + (size_t)ub*G4 + hu0 + uj;

    for (int t = 0; t < T_STEPS; t++){
        // prefetch gate inputs early (independent of h)
        const float* gin = ginp + (size_t)t*BSZ*G4;
        float g0 = gin[0];
        float g1 = gin[HID];
        float g2 = gin[2*HID];
        float g3 = gin[3*HID];

        float acc[2][4][4];
        #pragma unroll
        for (int mt = 0; mt < 2; mt++)
            #pragma unroll
            for (int g = 0; g < 4; g++)
                #pragma unroll
                for (int j = 0; j < 4; j++) acc[mt][g][j] = 0.f;

        if (t > 0){
            const __nv_bfloat16* hhi = hb + (size_t)(t & 1) * (2*BSZ*HID);
            const __nv_bfloat16* hlo = hhi + BSZ*HID;
            #pragma unroll 2
            for (int kt = 0; kt < 8; kt++){
                const int kk = wk0 + kt*16 + qc;
                uint32_t ah[2][4], al[2][4];
                #pragma unroll
                for (int mt = 0; mt < 2; mt++){
                    const int r = mt*16 + qr;
                    ah[mt][0] = *(const uint32_t*)(hhi + r*HID + kk);
                    ah[mt][1] = *(const uint32_t*)(hhi + (r+8)*HID + kk);
                    ah[mt][2] = *(const uint32_t*)(hhi + r*HID + kk + 8);
                    ah[mt][3] = *(const uint32_t*)(hhi + (r+8)*HID + kk + 8);
                    al[mt][0] = *(const uint32_t*)(hlo + r*HID + kk);
                    al[mt][1] = *(const uint32_t*)(hlo + (r+8)*HID + kk);
                    al[mt][2] = *(const uint32_t*)(hlo + r*HID + kk + 8);
                    al[mt][3] = *(const uint32_t*)(hlo + (r+8)*HID + kk + 8);
                }
                #pragma unroll
                for (int mt = 0; mt < 2; mt++)
                    #pragma unroll
                    for (int g = 0; g < 4; g++){
                        mma16816(acc[mt][g], ah[mt], bh[g][kt]);
                        mma16816(acc[mt][g], ah[mt], bl[g][kt]);
                        mma16816(acc[mt][g], al[mt], bh[g][kt]);
                    }
            }
        }

        // split-k partials -> smem
        #pragma unroll
        for (int mt = 0; mt < 2; mt++)
            #pragma unroll
            for (int g = 0; g < 4; g++){
                const int r = mt*16 + qr;
                *(float2*)&red[w][r][g*8 + qc]   = make_float2(acc[mt][g][0], acc[mt][g][1]);
                *(float2*)&red[w][r+8][g*8 + qc] = make_float2(acc[mt][g][2], acc[mt][g][3]);
            }
        __syncthreads();

        // state update: thread = (batch ub, unit uj)
        {
            float sg[4] = {0.f, 0.f, 0.f, 0.f};
            #pragma unroll
            for (int ww = 0; ww < 8; ww++)
                #pragma unroll
                for (int g = 0; g < 4; g++)
                    sg[g] += red[ww][ub][g*8 + uj];

            float iv = sg[0] + g0;
            float gv = sg[1] + g1;
            float fv = sg[2] + g2;
            float ov = sg[3] + g3;
            float cp = sc[uj][ub];
            float cv = sigm(fv + 1.0f) * cp + sigm(iv) * tanhf(gv);
            float hv = sigm(ov) * tanhf(cv);
            sc[uj][ub] = cv;

            __nv_bfloat16 hhv = __float2bfloat16(hv);
            __nv_bfloat16 hlv = __float2bfloat16(hv - __bfloat162float(hhv));
            // next-step exchange buffer
            __nv_bfloat16* wbuf = hb + (size_t)((t+1) & 1) * (2*BSZ*HID);
            wbuf[ub*HID + hu0 + uj]           = hhv;
            wbuf[BSZ*HID + ub*HID + hu0 + uj] = hlv;
            // layer output = next GEMM's A operand (already split)
            const size_t orow = (size_t)(t*BSZ + ub)*HID + hu0 + uj;
            ohi[orow] = hhv;
            olo[orow] = hlv;
        }

        // grid barrier (publishes h(t))
        __syncthreads();
        if (tid == 0){
            __threadfence();
            atomicAdd(&g_ctr1, 1ULL);
            const unsigned long long target = base + (unsigned long long)(t+1)*NBLK;
            while (*(volatile unsigned long long*)&g_ctr1 < target) __nanosleep(64);
            __threadfence();
        }
        __syncthreads();
    }
}

// ---------------- launch ----------------
extern "C" void kernel_launch(void* const* d_in, const int* in_sizes, int n_in,
                              void* d_out, int out_size){
    (void)in_sizes; (void)n_in; (void)out_size;
    const int*   data = (const int*)d_in[0];
    const float* emb  = (const float*)d_in[2];
    const float* W[3]  = {(const float*)d_in[3], (const float*)d_in[5], (const float*)d_in[7]};
    const float* bs[3] = {(const float*)d_in[4], (const float*)d_in[6], (const float*)d_in[8]};
    const float* Wd = (const float*)d_in[9];
    const float* bd = (const float*)d_in[10];

    float *gates;
    __nv_bfloat16 *ahi, *alo, *wthi, *wtlo, *whthi, *whtlo, *wdthi, *wdtlo, *hb;
    cudaGetSymbolAddress((void**)&gates, g_gates);
    cudaGetSymbolAddress((void**)&ahi,   g_ahi);
    cudaGetSymbolAddress((void**)&alo,   g_alo);
    cudaGetSymbolAddress((void**)&wthi,  g_wthi);
    cudaGetSymbolAddress((void**)&wtlo,  g_wtlo);
    cudaGetSymbolAddress((void**)&whthi, g_whthi);
    cudaGetSymbolAddress((void**)&whtlo, g_whtlo);
    cudaGetSymbolAddress((void**)&wdthi, g_wdthi);
    cudaGetSymbolAddress((void**)&wdtlo, g_wdtlo);
    cudaGetSymbolAddress((void**)&hb,    g_hb);

    cudaFuncSetAttribute(gemm_mma, cudaFuncAttributeMaxDynamicSharedMemorySize, MMA_SMEM);

    // 1) embedding gather + split directly into A operand
    embed_split<<<TB*EMB/4/256, 256>>>(data, emb, ahi, alo);

    for (int L = 0; L < 3; L++){
        int Din = (L == 0) ? EMB : HID;
        // input projection on tensor cores (A = ahi/alo from previous stage)
        wtr_k<<<dim3(G4/32, Din/32), dim3(32, 8)>>>(W[L], wthi, wtlo, Din, G4);
        gemm_mma<<<dim3(TB/128, G4/128), 256, MMA_SMEM>>>(
            ahi, alo, wthi, wtlo, bs[L], gates, TB, G4, Din);
        // recurrent weights -> bf16 split, then persistent tensor-core recurrence.
        // lstm overwrites ahi/alo with this layer's output (split) for the next GEMM.
        const float* Wh = W[L] + (size_t)Din * G4;
        wtr_k<<<dim3(G4/32, HID/32), dim3(32, 8)>>>(Wh, whthi, whtlo, HID, G4);
        lstm_layer_mma<<<NBLK, 256>>>(gates, whthi, whtlo, ahi, alo, hb);
    }

    // 2) decoder on tensor cores
    wtr_k<<<dim3(VOCAB/32, HID/32), dim3(32, 8)>>>(Wd, wdthi, wdtlo, HID, VOCAB);
    gemm_mma<<<dim3(TB/128, VOCAB/128), 256, MMA_SMEM>>>(
        ahi, alo, wdthi, wdtlo, bd, (float*)d_out, TB, VOCAB, HID);
}

// round 9
// speedup vs baseline: 1.4901x; 1.4901x over previous
#include <cuda_runtime.h>
#include <cuda_bf16.h>
#include <math.h>
#include <cstdint>

#define T_STEPS 256
#define BSZ 32
#define VOCAB 32000
#define EMB 512
#define HID 1024
#define G4 4096
#define TB (T_STEPS*BSZ)   // 8192
#define NBLK 128

// ---------------- scratch (device globals; no allocation allowed) ----------------
__device__ float g_gates[(size_t)TB*G4];             // 134 MB input-projection gates
__device__ __nv_bfloat16 g_ahi[(size_t)TB*HID];      // A split hi (activations, reused per layer)
__device__ __nv_bfloat16 g_alo[(size_t)TB*HID];      // A split lo
__device__ __nv_bfloat16 g_wthi[(size_t)G4*HID];     // layer Wx^T hi
__device__ __nv_bfloat16 g_wtlo[(size_t)G4*HID];     // layer Wx^T lo
__device__ __nv_bfloat16 g_whthi[(size_t)G4*HID];    // layer Wh^T hi
__device__ __nv_bfloat16 g_whtlo[(size_t)G4*HID];    // layer Wh^T lo
__device__ __nv_bfloat16 g_wdthi[(size_t)VOCAB*HID]; // decoder W^T hi
__device__ __nv_bfloat16 g_wdtlo[(size_t)VOCAB*HID]; // decoder W^T lo
__device__ __nv_bfloat16 g_hb[2*2*BSZ*HID];          // h bf16 [par][hi/lo][32*1024]

// monotonic grid-barrier counter
__device__ unsigned long long g_ctr1;

// ---------------- helpers ----------------
__device__ __forceinline__ uint32_t smem_u32(const void* p){
    uint32_t a; asm("{ .reg .u64 t; cvta.to.shared.u64 t, %1; cvt.u32.u64 %0, t; }" : "=r"(a) : "l"(p));
    return a;
}
#define CP_ASYNC16(dst, src) asm volatile("cp.async.cg.shared.global [%0], [%1], 16;" :: "r"(dst), "l"(src))
#define CP_COMMIT()  asm volatile("cp.async.commit_group;" ::: "memory")

__device__ __forceinline__ void ldsm4(uint32_t* r, uint32_t addr){
    asm volatile("ldmatrix.sync.aligned.m8n8.x4.shared.b16 {%0,%1,%2,%3}, [%4];"
        : "=r"(r[0]), "=r"(r[1]), "=r"(r[2]), "=r"(r[3]) : "r"(addr));
}
__device__ __forceinline__ void mma16816(float* c, const uint32_t* a, const uint32_t* b){
    asm volatile("mma.sync.aligned.m16n8k16.row.col.f32.bf16.bf16.f32 "
        "{%0,%1,%2,%3}, {%4,%5,%6,%7}, {%8,%9}, {%0,%1,%2,%3};"
        : "+f"(c[0]), "+f"(c[1]), "+f"(c[2]), "+f"(c[3])
        : "r"(a[0]), "r"(a[1]), "r"(a[2]), "r"(a[3]), "r"(b[0]), "r"(b[1]));
}
__device__ __forceinline__ float sigm(float x){ return 1.0f / (1.0f + expf(-x)); }

// ---------------- embedding gather + bf16 hi/lo split ----------------
__global__ void embed_split(const int* __restrict__ data, const float* __restrict__ emb,
                            __nv_bfloat16* __restrict__ hi, __nv_bfloat16* __restrict__ lo){
    int idx = blockIdx.x * 256 + threadIdx.x;     // over TB*EMB/4 float4s
    int e4 = idx & (EMB/4 - 1);
    int tb = idx >> 7;                            // EMB/4 = 128
    float4 v = ((const float4*)(emb + (size_t)data[tb]*EMB))[e4];
    __nv_bfloat16 h0 = __float2bfloat16(v.x), h1 = __float2bfloat16(v.y);
    __nv_bfloat16 h2 = __float2bfloat16(v.z), h3 = __float2bfloat16(v.w);
    __nv_bfloat16 l0 = __float2bfloat16(v.x - __bfloat162float(h0));
    __nv_bfloat16 l1 = __float2bfloat16(v.y - __bfloat162float(h1));
    __nv_bfloat16 l2 = __float2bfloat16(v.z - __bfloat162float(h2));
    __nv_bfloat16 l3 = __float2bfloat16(v.w - __bfloat162float(h3));
    ((__nv_bfloat162*)hi)[2*idx]   = __nv_bfloat162(h0, h1);
    ((__nv_bfloat162*)hi)[2*idx+1] = __nv_bfloat162(h2, h3);
    ((__nv_bfloat162*)lo)[2*idx]   = __nv_bfloat162(l0, l1);
    ((__nv_bfloat162*)lo)[2*idx+1] = __nv_bfloat162(l2, l3);
}

// ---------------- weight transpose + split: W[K,N] -> Wt_hi/lo[N,K] ----------------
__global__ void wtr_k(const float* __restrict__ W, __nv_bfloat16* __restrict__ thi,
                      __nv_bfloat16* __restrict__ tlo, int K, int N){
    __shared__ float s[32][33];
    int tx = threadIdx.x, ty = threadIdx.y;
    int n0 = blockIdx.x * 32, k0 = blockIdx.y * 32;
    #pragma unroll
    for (int j = 0; j < 32; j += 8)
        s[ty+j][tx] = W[(size_t)(k0+ty+j)*N + n0 + tx];
    __syncthreads();
    #pragma unroll
    for (int j = 0; j < 32; j += 8){
        float v = s[tx][ty+j];
        __nv_bfloat16 h = __float2bfloat16(v);
        __nv_bfloat16 l = __float2bfloat16(v - __bfloat162float(h));
        size_t o = (size_t)(n0+ty+j)*K + k0 + tx;
        thi[o] = h;
        tlo[o] = l;
    }
}

// ---------------- bf16 3-split GEMM on mma.sync ----------------
// 1D grid with grouped rasterization: groups of GRP n-tiles x all m-tiles,
// so the active B slice (GRP x 512KB) stays L2-resident while A streams once per group.
#define BKC 32
#define STRIDE 40
#define MAT_B (128*STRIDE*2)
#define BUF_BYTES (4*MAT_B)
#define MMA_SMEM (2*BUF_BYTES + 512)
#define GRP 16

__global__ __launch_bounds__(256)
void gemm_mma(const __nv_bfloat16* __restrict__ Ahi, const __nv_bfloat16* __restrict__ Alo,
              const __nv_bfloat16* __restrict__ Bhi, const __nv_bfloat16* __restrict__ Blo,
              const float* __restrict__ bias, float* __restrict__ C,
              int M, int N, int K)
{
    extern __shared__ char smem[];
    const uint32_t sb = smem_u32(smem);
    const int tid  = threadIdx.x;
    const int wid  = tid >> 5;
    const int lane = tid & 31;

    // grouped tile mapping
    const int tilesM = M >> 7, tilesN = N >> 7;
    const int per_group = GRP * tilesM;
    const int group = blockIdx.x / per_group;
    const int rem   = blockIdx.x - group * per_group;
    const int gn0   = group * GRP;
    int gw = tilesN - gn0; if (gw > GRP) gw = GRP;
    const int n0 = (gn0 + rem % gw) * 128;
    const int m0 = (rem / gw) * 128;

    const int warp_m = (wid & 3) * 32;
    const int warp_n = (wid >> 2) * 64;

    float* biasS = (float*)(smem + 2*BUF_BYTES);
    if (tid < 128) biasS[tid] = bias[n0 + tid];

    const int r0v = tid >> 2,          kv0 = (tid & 3) * 8;
    const int r1v = (tid + 256) >> 2,  kv1 = kv0;
    const uint32_t d0 = (uint32_t)(r0v*STRIDE + kv0) * 2;
    const uint32_t d1 = (uint32_t)(r1v*STRIDE + kv1) * 2;

    const __nv_bfloat16* a0p = Ahi + (size_t)(m0 + r0v)*K + kv0;
    const __nv_bfloat16* a1p = Ahi + (size_t)(m0 + r1v)*K + kv1;
    const __nv_bfloat16* l0p = Alo + (size_t)(m0 + r0v)*K + kv0;
    const __nv_bfloat16* l1p = Alo + (size_t)(m0 + r1v)*K + kv1;
    const __nv_bfloat16* b0p = Bhi + (size_t)(n0 + r0v)*K + kv0;
    const __nv_bfloat16* b1p = Bhi + (size_t)(n0 + r1v)*K + kv1;
    const __nv_bfloat16* c0p = Blo + (size_t)(n0 + r0v)*K + kv0;
    const __nv_bfloat16* c1p = Blo + (size_t)(n0 + r1v)*K + kv1;

    const int lq = lane >> 3, lr = lane & 7;
    uint32_t offA[2], offB[4];
    #pragma unroll
    for (int mt = 0; mt < 2; mt++)
        offA[mt] = (uint32_t)((warp_m + mt*16 + (lq&1)*8 + lr)*STRIDE + (lq>>1)*8) * 2;
    #pragma unroll
    for (int np = 0; np < 4; np++)
        offB[np] = (uint32_t)((warp_n + np*16 + (lq>>1)*8 + lr)*STRIDE + (lq&1)*8) * 2;

    float acc[2][8][4];
    #pragma unroll
    for (int mt = 0; mt < 2; mt++)
        #pragma unroll
        for (int nt = 0; nt < 8; nt++)
            #pragma unroll
            for (int j = 0; j < 4; j++) acc[mt][nt][j] = 0.f;

    const int NC = K / BKC;

    {
        uint32_t bb = sb;
        CP_ASYNC16(bb + 0*MAT_B + d0, a0p); CP_ASYNC16(bb + 0*MAT_B + d1, a1p);
        CP_ASYNC16(bb + 1*MAT_B + d0, l0p); CP_ASYNC16(bb + 1*MAT_B + d1, l1p);
        CP_ASYNC16(bb + 2*MAT_B + d0, b0p); CP_ASYNC16(bb + 2*MAT_B + d1, b1p);
        CP_ASYNC16(bb + 3*MAT_B + d0, c0p); CP_ASYNC16(bb + 3*MAT_B + d1, c1p);
        CP_COMMIT();
    }

    for (int c = 0; c < NC; c++){
        if (c + 1 < NC){
            uint32_t bb = sb + ((c+1) & 1) * BUF_BYTES;
            int ko = (c+1) * BKC;
            CP_ASYNC16(bb + 0*MAT_B + d0, a0p + ko); CP_ASYNC16(bb + 0*MAT_B + d1, a1p + ko);
            CP_ASYNC16(bb + 1*MAT_B + d0, l0p + ko); CP_ASYNC16(bb + 1*MAT_B + d1, l1p + ko);
            CP_ASYNC16(bb + 2*MAT_B + d0, b0p + ko); CP_ASYNC16(bb + 2*MAT_B + d1, b1p + ko);
            CP_ASYNC16(bb + 3*MAT_B + d0, c0p + ko); CP_ASYNC16(bb + 3*MAT_B + d1, c1p + ko);
            CP_COMMIT();
            asm volatile("cp.async.wait_group 1;" ::: "memory");
        } else {
            asm volatile("cp.async.wait_group 0;" ::: "memory");
        }
        __syncthreads();

        const uint32_t ab = sb + (c & 1) * BUF_BYTES;
        const uint32_t al = ab + MAT_B;
        const uint32_t bh = ab + 2*MAT_B;
        const uint32_t bl = ab + 3*MAT_B;

        #pragma unroll
        for (int ks = 0; ks < 2; ks++){
            const uint32_t ko = ks * 32;
            uint32_t rah[2][4], ral[2][4];
            #pragma unroll
            for (int mt = 0; mt < 2; mt++){
                ldsm4(rah[mt], ab + offA[mt] + ko);
                ldsm4(ral[mt], al + offA[mt] + ko);
            }
            uint32_t rbh[8][2], rbl[8][2];
            #pragma unroll
            for (int np = 0; np < 4; np++){
                uint32_t t[4];
                ldsm4(t, bh + offB[np] + ko);
                rbh[np*2][0] = t[0];   rbh[np*2][1] = t[1];
                rbh[np*2+1][0] = t[2]; rbh[np*2+1][1] = t[3];
                ldsm4(t, bl + offB[np] + ko);
                rbl[np*2][0] = t[0];   rbl[np*2][1] = t[1];
                rbl[np*2+1][0] = t[2]; rbl[np*2+1][1] = t[3];
            }
            #pragma unroll
            for (int mt = 0; mt < 2; mt++)
                #pragma unroll
                for (int nt = 0; nt < 8; nt++){
                    mma16816(acc[mt][nt], rah[mt], rbh[nt]);
                    mma16816(acc[mt][nt], rah[mt], rbl[nt]);
                    mma16816(acc[mt][nt], ral[mt], rbh[nt]);
                }
        }
        __syncthreads();
    }

    #pragma unroll
    for (int mt = 0; mt < 2; mt++){
        int row = m0 + warp_m + mt*16 + (lane >> 2);
        #pragma unroll
        for (int nt = 0; nt < 8; nt++){
            int lc = warp_n + nt*8 + (lane & 3)*2;
            float bA = biasS[lc], bB = biasS[lc+1];
            float2 v0 = make_float2(acc[mt][nt][0] + bA, acc[mt][nt][1] + bB);
            float2 v1 = make_float2(acc[mt][nt][2] + bA, acc[mt][nt][3] + bB);
            *(float2*)(C + (size_t)row*N + n0 + lc)       = v0;
            *(float2*)(C + (size_t)(row+8)*N + n0 + lc)   = v1;
        }
    }
}

// ---------------- persistent tensor-core LSTM layer ----------------
// 128 blocks, 256 thr / 8 warps. Block owns 32 gate cols (4 gates x 8 units).
// Wh^T bf16 fragments live in registers. h exchanged via small global double buffer.
// Layer output written directly as bf16 hi/lo rows of the next GEMM's A operand.
__global__ __launch_bounds__(256, 1)
void lstm_layer_mma(const float* __restrict__ gates_all,    // [T][32][4096]
                    const __nv_bfloat16* __restrict__ whhi,  // [4096][1024]
                    const __nv_bfloat16* __restrict__ whlo,
                    __nv_bfloat16* __restrict__ ohi,         // [T*32][1024] output split hi
                    __nv_bfloat16* __restrict__ olo,         // [T*32][1024] output split lo
                    __nv_bfloat16* __restrict__ hb)          // [2][2][32*1024]
{
    __shared__ float red[8][32][34];
    __shared__ float sc[8][33];
    __shared__ unsigned long long s_base;

    const int tid  = threadIdx.x;
    const int w    = tid >> 5;
    const int lane = tid & 31;
    const int hu0  = blockIdx.x * 8;
    const int wk0  = w * 128;
    const int qr   = lane >> 2;
    const int qc   = (lane & 3) * 2;

    // B fragments (Wh^T hi/lo), once per layer
    uint32_t bh[4][8][2], bl[4][8][2];
    #pragma unroll
    for (int g = 0; g < 4; g++){
        const size_t col = (size_t)(g*1024 + hu0 + qr);
        #pragma unroll
        for (int kt = 0; kt < 8; kt++){
            const size_t kk = (size_t)wk0 + kt*16 + qc;
            bh[g][kt][0] = *(const uint32_t*)(whhi + col*HID + kk);
            bh[g][kt][1] = *(const uint32_t*)(whhi + col*HID + kk + 8);
            bl[g][kt][0] = *(const uint32_t*)(whlo + col*HID + kk);
            bl[g][kt][1] = *(const uint32_t*)(whlo + col*HID + kk + 8);
        }
    }

    for (int i = tid; i < 8*33; i += 256) ((float*)sc)[i] = 0.f;
    if (tid == 0) s_base = *(volatile unsigned long long*)&g_ctr1;
    __syncthreads();
    const unsigned long long base = s_base;

    const int ub = tid & 31;    // update: batch
    const int uj = tid >> 5;    // update: unit 0..7
    const float* ginp = gates_all + (size_t)ub*G4 + hu0 + uj;

    for (int t = 0; t < T_STEPS; t++){
        // prefetch gate inputs early (independent of h)
        const float* gin = ginp + (size_t)t*BSZ*G4;
        float g0 = gin[0];
        float g1 = gin[HID];
        float g2 = gin[2*HID];
        float g3 = gin[3*HID];

        float acc[2][4][4];
        #pragma unroll
        for (int mt = 0; mt < 2; mt++)
            #pragma unroll
            for (int g = 0; g < 4; g++)
                #pragma unroll
                for (int j = 0; j < 4; j++) acc[mt][g][j] = 0.f;

        if (t > 0){
            const __nv_bfloat16* hhi = hb + (size_t)(t & 1) * (2*BSZ*HID);
            const __nv_bfloat16* hlo = hhi + BSZ*HID;
            #pragma unroll 2
            for (int kt = 0; kt < 8; kt++){
                const int kk = wk0 + kt*16 + qc;
                uint32_t ah[2][4], al[2][4];
                #pragma unroll
                for (int mt = 0; mt < 2; mt++){
                    const int r = mt*16 + qr;
                    ah[mt][0] = *(const uint32_t*)(hhi + r*HID + kk);
                    ah[mt][1] = *(const uint32_t*)(hhi + (r+8)*HID + kk);
                    ah[mt][2] = *(const uint32_t*)(hhi + r*HID + kk + 8);
                    ah[mt][3] = *(const uint32_t*)(hhi + (r+8)*HID + kk + 8);
                    al[mt][0] = *(const uint32_t*)(hlo + r*HID + kk);
                    al[mt][1] = *(const uint32_t*)(hlo + (r+8)*HID + kk);
                    al[mt][2] = *(const uint32_t*)(hlo + r*HID + kk + 8);
                    al[mt][3] = *(const uint32_t*)(hlo + (r+8)*HID + kk + 8);
                }
                #pragma unroll
                for (int mt = 0; mt < 2; mt++)
                    #pragma unroll
                    for (int g = 0; g < 4; g++){
                        mma16816(acc[mt][g], ah[mt], bh[g][kt]);
                        mma16816(acc[mt][g], ah[mt], bl[g][kt]);
                        mma16816(acc[mt][g], al[mt], bh[g][kt]);
                    }
            }
        }

        // split-k partials -> smem
        #pragma unroll
        for (int mt = 0; mt < 2; mt++)
            #pragma unroll
            for (int g = 0; g < 4; g++){
                const int r = mt*16 + qr;
                *(float2*)&red[w][r][g*8 + qc]   = make_float2(acc[mt][g][0], acc[mt][g][1]);
                *(float2*)&red[w][r+8][g*8 + qc] = make_float2(acc[mt][g][2], acc[mt][g][3]);
            }
        __syncthreads();

        // state update: thread = (batch ub, unit uj)
        {
            float sg[4] = {0.f, 0.f, 0.f, 0.f};
            #pragma unroll
            for (int ww = 0; ww < 8; ww++)
                #pragma unroll
                for (int g = 0; g < 4; g++)
                    sg[g] += red[ww][ub][g*8 + uj];

            float iv = sg[0] + g0;
            float gv = sg[1] + g1;
            float fv = sg[2] + g2;
            float ov = sg[3] + g3;
            float cp = sc[uj][ub];
            float cv = sigm(fv + 1.0f) * cp + sigm(iv) * tanhf(gv);
            float hv = sigm(ov) * tanhf(cv);
            sc[uj][ub] = cv;

            __nv_bfloat16 hhv = __float2bfloat16(hv);
            __nv_bfloat16 hlv = __float2bfloat16(hv - __bfloat162float(hhv));
            // next-step exchange buffer
            __nv_bfloat16* wbuf = hb + (size_t)((t+1) & 1) * (2*BSZ*HID);
            wbuf[ub*HID + hu0 + uj]           = hhv;
            wbuf[BSZ*HID + ub*HID + hu0 + uj] = hlv;
            // layer output = next GEMM's A operand (already split)
            const size_t orow = (size_t)(t*BSZ + ub)*HID + hu0 + uj;
            ohi[orow] = hhv;
            olo[orow] = hlv;
        }

        // grid barrier (publishes h(t))
        __syncthreads();
        if (tid == 0){
            __threadfence();
            atomicAdd(&g_ctr1, 1ULL);
            const unsigned long long target = base + (unsigned long long)(t+1)*NBLK;
            while (*(volatile unsigned long long*)&g_ctr1 < target) __nanosleep(64);
            __threadfence();
        }
        __syncthreads();
    }
}

// ---------------- launch ----------------
extern "C" void kernel_launch(void* const* d_in, const int* in_sizes, int n_in,
                              void* d_out, int out_size){
    (void)in_sizes; (void)n_in; (void)out_size;
    const int*   data = (const int*)d_in[0];
    const float* emb  = (const float*)d_in[2];
    const float* W[3]  = {(const float*)d_in[3], (const float*)d_in[5], (const float*)d_in[7]};
    const float* bs[3] = {(const float*)d_in[4], (const float*)d_in[6], (const float*)d_in[8]};
    const float* Wd = (const float*)d_in[9];
    const float* bd = (const float*)d_in[10];

    float *gates;
    __nv_bfloat16 *ahi, *alo, *wthi, *wtlo, *whthi, *whtlo, *wdthi, *wdtlo, *hb;
    cudaGetSymbolAddress((void**)&gates, g_gates);
    cudaGetSymbolAddress((void**)&ahi,   g_ahi);
    cudaGetSymbolAddress((void**)&alo,   g_alo);
    cudaGetSymbolAddress((void**)&wthi,  g_wthi);
    cudaGetSymbolAddress((void**)&wtlo,  g_wtlo);
    cudaGetSymbolAddress((void**)&whthi, g_whthi);
    cudaGetSymbolAddress((void**)&whtlo, g_whtlo);
    cudaGetSymbolAddress((void**)&wdthi, g_wdthi);
    cudaGetSymbolAddress((void**)&wdtlo, g_wdtlo);
    cudaGetSymbolAddress((void**)&hb,    g_hb);

    cudaFuncSetAttribute(gemm_mma, cudaFuncAttributeMaxDynamicSharedMemorySize, MMA_SMEM);

    // 1) embedding gather + split directly into A operand
    embed_split<<<TB*EMB/4/256, 256>>>(data, emb, ahi, alo);

    for (int L = 0; L < 3; L++){
        int Din = (L == 0) ? EMB : HID;
        // input projection on tensor cores (A = ahi/alo from previous stage)
        wtr_k<<<dim3(G4/32, Din/32), dim3(32, 8)>>>(W[L], wthi, wtlo, Din, G4);
        gemm_mma<<<(TB/128)*(G4/128), 256, MMA_SMEM>>>(
            ahi, alo, wthi, wtlo, bs[L], gates, TB, G4, Din);
        // recurrent weights -> bf16 split, then persistent tensor-core recurrence.
        // lstm overwrites ahi/alo with this layer's output (split) for the next GEMM.
        const float* Wh = W[L] + (size_t)Din * G4;
        wtr_k<<<dim3(G4/32, HID/32), dim3(32, 8)>>>(Wh, whthi, whtlo, HID, G4);
        lstm_layer_mma<<<NBLK, 256>>>(gates, whthi, whtlo, ahi, alo, hb);
    }

    // 2) decoder on tensor cores
    wtr_k<<<dim3(VOCAB/32, HID/32), dim3(32, 8)>>>(Wd, wdthi, wdtlo, HID, VOCAB);
    gemm_mma<<<(TB/128)*(VOCAB/128), 256, MMA_SMEM>>>(
        ahi, alo, wdthi, wdtlo, bd, (float*)d_out, TB, VOCAB, HID);
}